// round 14
// baseline (speedup 1.0000x reference)
#include <cuda_runtime.h>
#include <cuda_fp16.h>
#include <cstdint>

#define N_NODES 100000
#define N_EDGES 20000
#define NNZ     800000
#define D       128

// Scan tiling
#define SCAN_TPB   256
#define SCAN_PER   8
#define SCAN_CHUNK (SCAN_TPB * SCAN_PER)                      // 2048
#define NB1 ((N_EDGES + SCAN_CHUNK - 1) / SCAN_CHUNK)         // 10
#define NB2 ((N_NODES + SCAN_CHUNK - 1) / SCAN_CHUNK)         // 49
#define NBT (NB1 + NB2)                                       // 59

// ---------------------------------------------------------------------------
// Device-global scratch (allocation-free rule)
// ---------------------------------------------------------------------------
__device__ __align__(16) uint2 g_XH [N_NODES * 32]; // X fp16 (2x half2/lane), 25.6 MB
__device__ __align__(16) uint2 g_XeH[N_EDGES * 32]; // Xe fp16, 5.12 MB
__device__ __align__(16) uint2 g_XiH[N_NODES * 32]; // Xi fp16, 25.6 MB
__device__ __align__(16) float2 g_Wp[64 * 128];     // packed tf32 B fragments, 64 KB

__device__ int g1_cnt[N_EDGES];
__device__ int g1_off[N_EDGES + 1];
__device__ int g1_idx[NNZ];
__device__ __align__(16) int g1_rank[NNZ];          // rank-within-destination
__device__ int g2_cnt[N_NODES];
__device__ int g2_off[N_NODES + 1];
__device__ int g2_idx[NNZ];
__device__ __align__(16) int g2_rank[NNZ];

__device__ int g_blk_sum[NBT];
__device__ int g_ready;            // reset by prep each replay

// ---------------------------------------------------------------------------
// helpers
// ---------------------------------------------------------------------------
__device__ __forceinline__ uint32_t h2_to_u32(__half2 h) {
    return *reinterpret_cast<uint32_t*>(&h);
}
__device__ __forceinline__ __half2 u32_to_h2(uint32_t u) {
    return *reinterpret_cast<__half2*>(&u);
}
__device__ __forceinline__ uint32_t f2tf32(float f) {
    uint32_t r;
    asm("cvt.rna.tf32.f32 %0, %1;" : "=r"(r) : "f"(f));
    return r;
}
__device__ __forceinline__ void acc_h(float4& acc, uint2 r) {
    float2 f0 = __half22float2(u32_to_h2(r.x));
    float2 f1 = __half22float2(u32_to_h2(r.y));
    acc.x += f0.x; acc.y += f0.y; acc.z += f1.x; acc.w += f1.y;
}

// ---------------------------------------------------------------------------
// Prep: zero counters + ready flag (blocks 0..390) + W prep (391..422)
// ---------------------------------------------------------------------------
#define ZERO_BLKS ((N_NODES + 255) / 256)        // 391
#define WPREP_BLKS 32

__global__ void prep_kernel(const float* __restrict__ W) {
    if (blockIdx.x < ZERO_BLKS) {
        int i = blockIdx.x * blockDim.x + threadIdx.x;
        if (i < N_EDGES) g1_cnt[i] = 0;
        if (i < N_NODES) g2_cnt[i] = 0;
        if (i == 0) g_ready = 0;
    } else {
        int p = (blockIdx.x - ZERO_BLKS) * blockDim.x + threadIdx.x;  // 8192 total
        if (p < 64 * 128) {
            int n = p & 127;
            int tig = (p >> 7) & 3;
            int kk = p >> 9;
            float w0 = __ldg(W + n * 128 + kk * 8 + tig);
            float w1 = __ldg(W + n * 128 + kk * 8 + tig + 4);
            float2 o;
            o.x = __uint_as_float(f2tf32(w0));
            o.y = __uint_as_float(f2tf32(w1));
            g_Wp[p] = o;
        }
    }
}

// ---------------------------------------------------------------------------
// Histogram + rank recording, both graphs (int4), PLUS X->fp16 conversion
// (grid-stride; streams while atomics serialize — complementary resources).
// ---------------------------------------------------------------------------
#define HIST_BLKS ((NNZ / 4 + 255) / 256)        // 782

__global__ void hist_kernel(const int4* __restrict__ g1d4,
                            const int4* __restrict__ g2d4,
                            const float4* __restrict__ X4) {
    int i = blockIdx.x * blockDim.x + threadIdx.x;
    if (i < NNZ / 4) {
        int4 d1 = __ldg(g1d4 + i);
        int4 r1;
        r1.x = atomicAdd(&g1_cnt[d1.x], 1);
        r1.y = atomicAdd(&g1_cnt[d1.y], 1);
        r1.z = atomicAdd(&g1_cnt[d1.z], 1);
        r1.w = atomicAdd(&g1_cnt[d1.w], 1);
        reinterpret_cast<int4*>(g1_rank)[i] = r1;
        int4 d2 = __ldg(g2d4 + i);
        int4 r2;
        r2.x = atomicAdd(&g2_cnt[d2.x], 1);
        r2.y = atomicAdd(&g2_cnt[d2.y], 1);
        r2.z = atomicAdd(&g2_cnt[d2.z], 1);
        r2.w = atomicAdd(&g2_cnt[d2.w], 1);
        reinterpret_cast<int4*>(g2_rank)[i] = r2;
    }
    // X -> fp16 (3.2M float4 granules, ~16 per thread), overlaps atomic drain
    const int nthr = HIST_BLKS * 256;
    for (int j = i; j < N_NODES * 32; j += nthr) {
        float4 v = __ldg(X4 + j);
        uint2 o;
        o.x = h2_to_u32(__floats2half2_rn(v.x, v.y));
        o.y = h2_to_u32(__floats2half2_rn(v.z, v.w));
        g_XH[j] = o;
    }
}

// ---------------------------------------------------------------------------
// Fused scan: single launch, 59 blocks (all co-resident; 59 < 148 SMs).
// ---------------------------------------------------------------------------
__global__ void scan_fused_kernel() {
    const int bid = blockIdx.x;
    const int t = threadIdx.x;
    const int* cnt; int* off; int n, lbase;
    if (bid < NB1) { cnt = g1_cnt; off = g1_off; n = N_EDGES; lbase = bid * SCAN_CHUNK; }
    else           { cnt = g2_cnt; off = g2_off; n = N_NODES; lbase = (bid - NB1) * SCAN_CHUNK; }

    int c[SCAN_PER];
    int s = 0;
    const int i0 = lbase + t * SCAN_PER;
#pragma unroll
    for (int k = 0; k < SCAN_PER; k++) {
        int i = i0 + k;
        c[k] = (i < n) ? cnt[i] : 0;
        s += c[k];
    }

    const int lane = t & 31, wid = t >> 5;
    int v = s;
#pragma unroll
    for (int o = 1; o < 32; o <<= 1) {
        int u = __shfl_up_sync(0xffffffffu, v, o);
        if (lane >= o) v += u;
    }
    __shared__ int ws[8];
    if (lane == 31) ws[wid] = v;
    __syncthreads();
    if (t < 8) {
        int w = ws[t];
#pragma unroll
        for (int o = 1; o < 8; o <<= 1) {
            int u = __shfl_up_sync(0xffu, w, o);
            if (t >= o) w += u;
        }
        ws[t] = w;
    }
    __syncthreads();

    int excl = v - s + (wid ? ws[wid - 1] : 0);
    if (t == SCAN_TPB - 1) {
        g_blk_sum[bid] = excl + s;
        __threadfence();
        atomicAdd(&g_ready, 1);
    }

    if (t == 0) {
        volatile int* rdy = &g_ready;
        while (*rdy < NBT) { }
    }
    __syncthreads();
    __threadfence();

    __shared__ int be[64];
    __shared__ int wtot;
    if (t < 64) {
        int bv = (t < NBT) ? g_blk_sum[t] : 0;
        int bs = bv;
#pragma unroll
        for (int o = 1; o < 32; o <<= 1) {
            int u = __shfl_up_sync(0xffffffffu, bs, o);
            if ((t & 31) >= o) bs += u;
        }
        if (t == 31) wtot = bs;
        be[t] = bs - bv;
    }
    __syncthreads();
    if (t >= 32 && t < 64) be[t] += wtot;
    __syncthreads();

    int base = be[bid] + excl;
    if (bid >= NB1) base -= NNZ;
#pragma unroll
    for (int k = 0; k < SCAN_PER; k++) {
        int i = i0 + k;
        if (i < n) {
            off[i] = base;
            base += c[k];
        }
    }
    if (bid == 0 && t == 0) {
        g1_off[N_EDGES] = NNZ;
        g2_off[N_NODES] = NNZ;
    }
}

// ---------------------------------------------------------------------------
// Fill — atomic-free, 4 nnz/thread/graph (int4 loads): 8 parallel chains
// ---------------------------------------------------------------------------
__global__ void fill_kernel(const int4* __restrict__ g1s4, const int4* __restrict__ g1d4,
                            const int4* __restrict__ g2s4, const int4* __restrict__ g2d4) {
    int i = blockIdx.x * blockDim.x + threadIdx.x;
    if (i >= NNZ / 4) return;
    int4 s1 = __ldg(g1s4 + i);
    int4 d1 = __ldg(g1d4 + i);
    int4 r1 = reinterpret_cast<const int4*>(g1_rank)[i];
    int4 s2 = __ldg(g2s4 + i);
    int4 d2 = __ldg(g2d4 + i);
    int4 r2 = reinterpret_cast<const int4*>(g2_rank)[i];
    int o1x = g1_off[d1.x], o1y = g1_off[d1.y], o1z = g1_off[d1.z], o1w = g1_off[d1.w];
    int o2x = g2_off[d2.x], o2y = g2_off[d2.y], o2z = g2_off[d2.z], o2w = g2_off[d2.w];
    g1_idx[o1x + r1.x] = s1.x;
    g1_idx[o1y + r1.y] = s1.y;
    g1_idx[o1z + r1.z] = s1.z;
    g1_idx[o1w + r1.w] = s1.w;
    g2_idx[o2x + r2.x] = s2.x;
    g2_idx[o2y + r2.y] = s2.y;
    g2_idx[o2z + r2.z] = s2.z;
    g2_idx[o2w + r2.w] = s2.w;
}

// ---------------------------------------------------------------------------
// SpMM 1: XeH[e] = fp16( degE[e] * sum XH[s] )   (warp/edge, fp16 gather, u8)
// ---------------------------------------------------------------------------
__global__ void spmm1_kernel(const float* __restrict__ degE) {
    int e = (blockIdx.x * blockDim.x + threadIdx.x) >> 5;
    if (e >= N_EDGES) return;
    int lane = threadIdx.x & 31;
    int beg = g1_off[e], end = g1_off[e + 1];

    float4 acc = make_float4(0.f, 0.f, 0.f, 0.f);
    int j = beg;
    for (; j + 8 <= end; j += 8) {
        int s0 = g1_idx[j],     s1 = g1_idx[j + 1], s2 = g1_idx[j + 2], s3 = g1_idx[j + 3];
        int s4 = g1_idx[j + 4], s5 = g1_idx[j + 5], s6 = g1_idx[j + 6], s7 = g1_idx[j + 7];
        uint2 r0 = g_XH[s0 * 32 + lane];
        uint2 r1 = g_XH[s1 * 32 + lane];
        uint2 r2 = g_XH[s2 * 32 + lane];
        uint2 r3 = g_XH[s3 * 32 + lane];
        uint2 r4 = g_XH[s4 * 32 + lane];
        uint2 r5 = g_XH[s5 * 32 + lane];
        uint2 r6 = g_XH[s6 * 32 + lane];
        uint2 r7 = g_XH[s7 * 32 + lane];
        acc_h(acc, r0); acc_h(acc, r1); acc_h(acc, r2); acc_h(acc, r3);
        acc_h(acc, r4); acc_h(acc, r5); acc_h(acc, r6); acc_h(acc, r7);
    }
    for (; j < end; j++) {
        int s = g1_idx[j];
        acc_h(acc, g_XH[s * 32 + lane]);
    }
    float de = __ldg(degE + e);
    uint2 o;
    o.x = h2_to_u32(__floats2half2_rn(acc.x * de, acc.y * de));
    o.y = h2_to_u32(__floats2half2_rn(acc.z * de, acc.w * de));
    g_XeH[e * 32 + lane] = o;
}

// ---------------------------------------------------------------------------
// SpMM 2 + residual: XiH[v] = fp16( (1-a)*degV[v]*sum XeH[s] + a*X0[v] )
// ---------------------------------------------------------------------------
__global__ void spmm2_kernel(const float4* __restrict__ X04,
                             const float* __restrict__ degV,
                             const float* __restrict__ alpha) {
    int v = (blockIdx.x * blockDim.x + threadIdx.x) >> 5;
    if (v >= N_NODES) return;
    int lane = threadIdx.x & 31;
    int beg = g2_off[v], end = g2_off[v + 1];

    float4 acc = make_float4(0.f, 0.f, 0.f, 0.f);
    int j = beg;
    for (; j + 8 <= end; j += 8) {
        int s0 = g2_idx[j],     s1 = g2_idx[j + 1], s2 = g2_idx[j + 2], s3 = g2_idx[j + 3];
        int s4 = g2_idx[j + 4], s5 = g2_idx[j + 5], s6 = g2_idx[j + 6], s7 = g2_idx[j + 7];
        uint2 r0 = g_XeH[s0 * 32 + lane];
        uint2 r1 = g_XeH[s1 * 32 + lane];
        uint2 r2 = g_XeH[s2 * 32 + lane];
        uint2 r3 = g_XeH[s3 * 32 + lane];
        uint2 r4 = g_XeH[s4 * 32 + lane];
        uint2 r5 = g_XeH[s5 * 32 + lane];
        uint2 r6 = g_XeH[s6 * 32 + lane];
        uint2 r7 = g_XeH[s7 * 32 + lane];
        acc_h(acc, r0); acc_h(acc, r1); acc_h(acc, r2); acc_h(acc, r3);
        acc_h(acc, r4); acc_h(acc, r5); acc_h(acc, r6); acc_h(acc, r7);
    }
    for (; j + 4 <= end; j += 4) {
        int s0 = g2_idx[j], s1 = g2_idx[j + 1], s2 = g2_idx[j + 2], s3 = g2_idx[j + 3];
        uint2 r0 = g_XeH[s0 * 32 + lane];
        uint2 r1 = g_XeH[s1 * 32 + lane];
        uint2 r2 = g_XeH[s2 * 32 + lane];
        uint2 r3 = g_XeH[s3 * 32 + lane];
        acc_h(acc, r0); acc_h(acc, r1); acc_h(acc, r2); acc_h(acc, r3);
    }
    for (; j < end; j++) {
        int s = g2_idx[j];
        acc_h(acc, g_XeH[s * 32 + lane]);
    }
    float a = __ldg(alpha);
    float sc = (1.f - a) * __ldg(degV + v);
    float4 x0 = __ldg(X04 + v * 32 + lane);
    float xi0 = sc * acc.x + a * x0.x;
    float xi1 = sc * acc.y + a * x0.y;
    float xi2 = sc * acc.z + a * x0.z;
    float xi3 = sc * acc.w + a * x0.w;
    uint2 o;
    o.x = h2_to_u32(__floats2half2_rn(xi0, xi1));
    o.y = h2_to_u32(__floats2half2_rn(xi2, xi3));
    g_XiH[v * 32 + lane] = o;
}

// ---------------------------------------------------------------------------
// GEMM: out = (1-b)*Xi + b*(Xi @ W^T)   (Xi fp16 in g_XiH; exact 16-row tiling)
// ---------------------------------------------------------------------------
#define XI_STRIDE 132

__global__ void __launch_bounds__(256, 2)
gemm_kernel(const float* __restrict__ beta, float* __restrict__ out) {
    __shared__ float Xism[16 * XI_STRIDE];

    const int tid = threadIdx.x;
    const int row0 = blockIdx.x * 16;
    const float bb = __ldg(beta);
    const float omb = 1.f - bb;

    const int warp = tid >> 5, lane = tid & 31;
    const int gid = lane >> 2, tig = lane & 3;
    const int nt0 = warp, nt1 = warp + 8;

    float2 bf0[16], bf1[16];
#pragma unroll
    for (int kk = 0; kk < 16; kk++) {
        bf0[kk] = __ldg(&g_Wp[(kk * 4 + tig) * 128 + nt0 * 8 + gid]);
        bf1[kk] = __ldg(&g_Wp[(kk * 4 + tig) * 128 + nt1 * 8 + gid]);
    }

    // Stage Xi tile: fp16 global -> fp32 smem
#pragma unroll
    for (int i = tid; i < 16 * 32; i += 256) {
        int r = i >> 5, c4 = i & 31;
        uint2 h = g_XiH[(row0 + r) * 32 + c4];
        float2 f0 = __half22float2(u32_to_h2(h.x));
        float2 f1 = __half22float2(u32_to_h2(h.y));
        float4 xi = make_float4(f0.x, f0.y, f1.x, f1.y);
        *reinterpret_cast<float4*>(&Xism[r * XI_STRIDE + c4 * 4]) = xi;
    }
    __syncthreads();

    float c00 = 0.f, c01 = 0.f, c02 = 0.f, c03 = 0.f;
    float c10 = 0.f, c11 = 0.f, c12 = 0.f, c13 = 0.f;

#pragma unroll
    for (int kk = 0; kk < 16; kk++) {
        int c = kk * 8 + tig;
        uint32_t a0 = f2tf32(Xism[gid * XI_STRIDE + c]);
        uint32_t a1 = f2tf32(Xism[(gid + 8) * XI_STRIDE + c]);
        uint32_t a2 = f2tf32(Xism[gid * XI_STRIDE + c + 4]);
        uint32_t a3 = f2tf32(Xism[(gid + 8) * XI_STRIDE + c + 4]);
        uint32_t b00 = __float_as_uint(bf0[kk].x);
        uint32_t b01 = __float_as_uint(bf0[kk].y);
        uint32_t b10 = __float_as_uint(bf1[kk].x);
        uint32_t b11 = __float_as_uint(bf1[kk].y);
        asm volatile(
            "mma.sync.aligned.m16n8k8.row.col.f32.tf32.tf32.f32 "
            "{%0,%1,%2,%3}, {%4,%5,%6,%7}, {%8,%9}, {%0,%1,%2,%3};"
            : "+f"(c00), "+f"(c01), "+f"(c02), "+f"(c03)
            : "r"(a0), "r"(a1), "r"(a2), "r"(a3), "r"(b00), "r"(b01));
        asm volatile(
            "mma.sync.aligned.m16n8k8.row.col.f32.tf32.tf32.f32 "
            "{%0,%1,%2,%3}, {%4,%5,%6,%7}, {%8,%9}, {%0,%1,%2,%3};"
            : "+f"(c10), "+f"(c11), "+f"(c12), "+f"(c13)
            : "r"(a0), "r"(a1), "r"(a2), "r"(a3), "r"(b10), "r"(b11));
    }

    const int r0 = row0 + gid;
    const int r1 = r0 + 8;
    {
        int col = nt0 * 8 + 2 * tig;
        float xi0 = Xism[gid * XI_STRIDE + col];
        float xi1 = Xism[gid * XI_STRIDE + col + 1];
        *reinterpret_cast<float2*>(out + (long)r0 * 128 + col) =
            make_float2(omb * xi0 + bb * c00, omb * xi1 + bb * c01);
        xi0 = Xism[(gid + 8) * XI_STRIDE + col];
        xi1 = Xism[(gid + 8) * XI_STRIDE + col + 1];
        *reinterpret_cast<float2*>(out + (long)r1 * 128 + col) =
            make_float2(omb * xi0 + bb * c02, omb * xi1 + bb * c03);

        col = nt1 * 8 + 2 * tig;
        xi0 = Xism[gid * XI_STRIDE + col];
        xi1 = Xism[gid * XI_STRIDE + col + 1];
        *reinterpret_cast<float2*>(out + (long)r0 * 128 + col) =
            make_float2(omb * xi0 + bb * c10, omb * xi1 + bb * c11);
        xi0 = Xism[(gid + 8) * XI_STRIDE + col];
        xi1 = Xism[(gid + 8) * XI_STRIDE + col + 1];
        *reinterpret_cast<float2*>(out + (long)r1 * 128 + col) =
            make_float2(omb * xi0 + bb * c12, omb * xi1 + bb * c13);
    }
}

// ---------------------------------------------------------------------------
// kernel_launch — 7 launches; X conversion hidden in hist's atomic shadow
// ---------------------------------------------------------------------------
extern "C" void kernel_launch(void* const* d_in, const int* in_sizes, int n_in,
                              void* d_out, int out_size) {
    const float* X     = (const float*)d_in[0];
    const float* X0    = (const float*)d_in[1];
    const float* degE  = (const float*)d_in[2];
    const float* degV  = (const float*)d_in[3];
    const float* alpha = (const float*)d_in[4];
    const float* beta  = (const float*)d_in[5];
    const float* W     = (const float*)d_in[6];
    const int*   g1s   = (const int*)d_in[7];
    const int*   g1d   = (const int*)d_in[8];
    const int*   g2s   = (const int*)d_in[9];
    const int*   g2d   = (const int*)d_in[10];
    float* out = (float*)d_out;

    // zero counters + ready flag + W prep
    prep_kernel<<<ZERO_BLKS + WPREP_BLKS, 256>>>(W);

    // CSR build: rank-recording hist (+ hidden X->fp16) -> fused scan -> fill
    hist_kernel<<<HIST_BLKS, 256>>>((const int4*)g1d, (const int4*)g2d, (const float4*)X);
    scan_fused_kernel<<<NBT, SCAN_TPB>>>();
    fill_kernel<<<(NNZ / 4 + 255) / 256, 256>>>((const int4*)g1s, (const int4*)g1d,
                                                (const int4*)g2s, (const int4*)g2d);

    // Gather-sum SpMMs (fp16 operands, fp32 accumulate)
    spmm1_kernel<<<(N_EDGES * 32 + 255) / 256, 256>>>(degE);
    spmm2_kernel<<<(N_NODES * 32 + 255) / 256, 256>>>((const float4*)X0, degV, alpha);

    // tf32 GEMM + residual epilogue (100000 = 6250 * 16 exact)
    gemm_kernel<<<N_NODES / 16, 256>>>(beta, out);
}

// round 15
// speedup vs baseline: 1.0119x; 1.0119x over previous
#include <cuda_runtime.h>
#include <cuda_fp16.h>
#include <cstdint>

#define N_NODES 100000
#define N_EDGES 20000
#define NNZ     800000
#define D       128

// Scan tiling
#define SCAN_TPB   256
#define SCAN_PER   8
#define SCAN_CHUNK (SCAN_TPB * SCAN_PER)                      // 2048
#define NB1 ((N_EDGES + SCAN_CHUNK - 1) / SCAN_CHUNK)         // 10
#define NB2 ((N_NODES + SCAN_CHUNK - 1) / SCAN_CHUNK)         // 49
#define NBT (NB1 + NB2)                                       // 59

#define MEGA_BLKS 592            // 148 SMs x 4 CTAs — wave-1 co-residency
#define MEGA_THREADS (MEGA_BLKS * 256)

// ---------------------------------------------------------------------------
// Device-global scratch (allocation-free rule)
// ---------------------------------------------------------------------------
__device__ __align__(16) uint2 g_XeH[N_EDGES * 32]; // Xe fp16 (2x half2/lane), 5.12 MB
__device__ __align__(16) uint2 g_XiH[N_NODES * 32]; // Xi fp16, 25.6 MB
__device__ __align__(16) float2 g_Wp[64 * 128];     // packed tf32 B fragments, 64 KB

__device__ int g1_cnt[N_EDGES];
__device__ int g1_off[N_EDGES + 1];
__device__ int g1_idx[NNZ];
__device__ __align__(16) int g1_rank[NNZ];          // rank-within-destination
__device__ int g2_cnt[N_NODES];
__device__ int g2_off[N_NODES + 1];
__device__ int g2_idx[NNZ];
__device__ __align__(16) int g2_rank[NNZ];

__device__ int g_blk_sum[NBT];
__device__ int g_bar;              // global barrier counter (reset by prep)

// ---------------------------------------------------------------------------
// helpers
// ---------------------------------------------------------------------------
__device__ __forceinline__ uint32_t h2_to_u32(__half2 h) {
    return *reinterpret_cast<uint32_t*>(&h);
}
__device__ __forceinline__ __half2 u32_to_h2(uint32_t u) {
    return *reinterpret_cast<__half2*>(&u);
}
__device__ __forceinline__ uint32_t f2tf32(float f) {
    uint32_t r;
    asm("cvt.rna.tf32.f32 %0, %1;" : "=r"(r) : "f"(f));
    return r;
}
__device__ __forceinline__ void acc_h(float4& acc, uint2 r) {
    float2 f0 = __half22float2(u32_to_h2(r.x));
    float2 f1 = __half22float2(u32_to_h2(r.y));
    acc.x += f0.x; acc.y += f0.y; acc.z += f1.x; acc.w += f1.y;
}

// Global spin barrier for co-resident grid (all MEGA_BLKS blocks).
// target = phase * MEGA_BLKS; g_bar reset to 0 by prep each replay.
__device__ __forceinline__ void grid_bar(int target) {
    __syncthreads();
    if (threadIdx.x == 0) {
        __threadfence();
        atomicAdd(&g_bar, 1);
        volatile int* b = &g_bar;
        while (*b < target) { }
    }
    __syncthreads();
    __threadfence();   // acquire
}

// ---------------------------------------------------------------------------
// Prep: zero counters + barrier reset (blocks 0..390) + W prep (391..422)
// ---------------------------------------------------------------------------
#define ZERO_BLKS ((N_NODES + 255) / 256)        // 391
#define WPREP_BLKS 32

__global__ void prep_kernel(const float* __restrict__ W) {
    if (blockIdx.x < ZERO_BLKS) {
        int i = blockIdx.x * blockDim.x + threadIdx.x;
        if (i < N_EDGES) g1_cnt[i] = 0;
        if (i < N_NODES) g2_cnt[i] = 0;
        if (i == 0) g_bar = 0;
    } else {
        int p = (blockIdx.x - ZERO_BLKS) * blockDim.x + threadIdx.x;  // 8192 total
        if (p < 64 * 128) {
            int n = p & 127;
            int tig = (p >> 7) & 3;
            int kk = p >> 9;
            float w0 = __ldg(W + n * 128 + kk * 8 + tig);
            float w1 = __ldg(W + n * 128 + kk * 8 + tig + 4);
            float2 o;
            o.x = __uint_as_float(f2tf32(w0));
            o.y = __uint_as_float(f2tf32(w1));
            g_Wp[p] = o;
        }
    }
}

// ---------------------------------------------------------------------------
// Fused CSR build: hist (rank-recording) -> scan -> fill, single launch.
// 592 blocks co-resident; 3 global spin barriers.
// ---------------------------------------------------------------------------
__global__ void __launch_bounds__(256, 4)
csr_kernel(const int4* __restrict__ g1d4, const int4* __restrict__ g2d4,
           const int2* __restrict__ g1s2, const int2* __restrict__ g1d2,
           const int2* __restrict__ g2s2, const int2* __restrict__ g2d2) {
    const int gtid = blockIdx.x * 256 + threadIdx.x;
    const int bid = blockIdx.x;
    const int t = threadIdx.x;

    // ---- Phase A: histogram + rank recording (grid-stride, int4) ----
    for (int i = gtid; i < NNZ / 4; i += MEGA_THREADS) {
        int4 d1 = __ldg(g1d4 + i);
        int4 r1;
        r1.x = atomicAdd(&g1_cnt[d1.x], 1);
        r1.y = atomicAdd(&g1_cnt[d1.y], 1);
        r1.z = atomicAdd(&g1_cnt[d1.z], 1);
        r1.w = atomicAdd(&g1_cnt[d1.w], 1);
        reinterpret_cast<int4*>(g1_rank)[i] = r1;
        int4 d2 = __ldg(g2d4 + i);
        int4 r2;
        r2.x = atomicAdd(&g2_cnt[d2.x], 1);
        r2.y = atomicAdd(&g2_cnt[d2.y], 1);
        r2.z = atomicAdd(&g2_cnt[d2.z], 1);
        r2.w = atomicAdd(&g2_cnt[d2.w], 1);
        reinterpret_cast<int4*>(g2_rank)[i] = r2;
    }
    grid_bar(MEGA_BLKS);           // hist complete

    // ---- Phase B1: per-chunk sums (blocks 0..NBT-1) ----
    int c[SCAN_PER];
    int excl = 0;
    int i0 = 0;
    const int* cnt = nullptr; int* off = nullptr; int n = 0;
    if (bid < NBT) {
        int lbase;
        if (bid < NB1) { cnt = g1_cnt; off = g1_off; n = N_EDGES; lbase = bid * SCAN_CHUNK; }
        else           { cnt = g2_cnt; off = g2_off; n = N_NODES; lbase = (bid - NB1) * SCAN_CHUNK; }
        i0 = lbase + t * SCAN_PER;
        int s = 0;
#pragma unroll
        for (int k = 0; k < SCAN_PER; k++) {
            int i = i0 + k;
            c[k] = (i < n) ? cnt[i] : 0;
            s += c[k];
        }
        const int lane = t & 31, wid = t >> 5;
        int v = s;
#pragma unroll
        for (int o = 1; o < 32; o <<= 1) {
            int u = __shfl_up_sync(0xffffffffu, v, o);
            if (lane >= o) v += u;
        }
        __shared__ int ws[8];
        if (lane == 31) ws[wid] = v;
        __syncthreads();
        if (t < 8) {
            int w = ws[t];
#pragma unroll
            for (int o = 1; o < 8; o <<= 1) {
                int u = __shfl_up_sync(0xffu, w, o);
                if (t >= o) w += u;
            }
            ws[t] = w;
        }
        __syncthreads();
        excl = v - s + (wid ? ws[wid - 1] : 0);
        if (t == SCAN_TPB - 1) g_blk_sum[bid] = excl + s;
    }
    grid_bar(2 * MEGA_BLKS);       // block sums published

    // ---- Phase B2: scan the 59 sums, write offsets (blocks 0..NBT-1) ----
    if (bid < NBT) {
        __shared__ int be[64];
        __shared__ int wtot;
        if (t < 64) {
            int bv = (t < NBT) ? g_blk_sum[t] : 0;
            int bs = bv;
#pragma unroll
            for (int o = 1; o < 32; o <<= 1) {
                int u = __shfl_up_sync(0xffffffffu, bs, o);
                if ((t & 31) >= o) bs += u;
            }
            if (t == 31) wtot = bs;
            be[t] = bs - bv;
        }
        __syncthreads();
        if (t >= 32 && t < 64) be[t] += wtot;
        __syncthreads();

        int base = be[bid] + excl;
        if (bid >= NB1) base -= NNZ;   // g2 segment rebase
#pragma unroll
        for (int k = 0; k < SCAN_PER; k++) {
            int i = i0 + k;
            if (i < n) {
                off[i] = base;
                base += c[k];
            }
        }
        if (bid == 0 && t == 0) {
            g1_off[N_EDGES] = NNZ;
            g2_off[N_NODES] = NNZ;
        }
    }
    grid_bar(3 * MEGA_BLKS);       // offsets ready

    // ---- Phase C: atomic-free fill (grid-stride, int2 = R13 layout) ----
    for (int i = gtid; i < NNZ / 2; i += MEGA_THREADS) {
        int2 s1 = __ldg(g1s2 + i);
        int2 d1 = __ldg(g1d2 + i);
        int2 r1 = *reinterpret_cast<const int2*>(g1_rank + 2 * i);
        g1_idx[g1_off[d1.x] + r1.x] = s1.x;
        g1_idx[g1_off[d1.y] + r1.y] = s1.y;
        int2 s2 = __ldg(g2s2 + i);
        int2 d2 = __ldg(g2d2 + i);
        int2 r2 = *reinterpret_cast<const int2*>(g2_rank + 2 * i);
        g2_idx[g2_off[d2.x] + r2.x] = s2.x;
        g2_idx[g2_off[d2.y] + r2.y] = s2.y;
    }
}

// ---------------------------------------------------------------------------
// SpMM 1: XeH[e] = fp16( degE[e] * sum X[s] )   (warp/edge, fp32 gather, u8)
// ---------------------------------------------------------------------------
__global__ void spmm1_kernel(const float4* __restrict__ X4,
                             const float* __restrict__ degE) {
    int e = (blockIdx.x * blockDim.x + threadIdx.x) >> 5;
    if (e >= N_EDGES) return;
    int lane = threadIdx.x & 31;
    int beg = g1_off[e], end = g1_off[e + 1];

    float4 acc = make_float4(0.f, 0.f, 0.f, 0.f);
    int j = beg;
    for (; j + 8 <= end; j += 8) {
        int s0 = g1_idx[j],     s1 = g1_idx[j + 1], s2 = g1_idx[j + 2], s3 = g1_idx[j + 3];
        int s4 = g1_idx[j + 4], s5 = g1_idx[j + 5], s6 = g1_idx[j + 6], s7 = g1_idx[j + 7];
        float4 v0 = __ldg(X4 + s0 * 32 + lane);
        float4 v1 = __ldg(X4 + s1 * 32 + lane);
        float4 v2 = __ldg(X4 + s2 * 32 + lane);
        float4 v3 = __ldg(X4 + s3 * 32 + lane);
        float4 v4 = __ldg(X4 + s4 * 32 + lane);
        float4 v5 = __ldg(X4 + s5 * 32 + lane);
        float4 v6 = __ldg(X4 + s6 * 32 + lane);
        float4 v7 = __ldg(X4 + s7 * 32 + lane);
        acc.x += ((v0.x + v1.x) + (v2.x + v3.x)) + ((v4.x + v5.x) + (v6.x + v7.x));
        acc.y += ((v0.y + v1.y) + (v2.y + v3.y)) + ((v4.y + v5.y) + (v6.y + v7.y));
        acc.z += ((v0.z + v1.z) + (v2.z + v3.z)) + ((v4.z + v5.z) + (v6.z + v7.z));
        acc.w += ((v0.w + v1.w) + (v2.w + v3.w)) + ((v4.w + v5.w) + (v6.w + v7.w));
    }
    for (; j < end; j++) {
        int s = g1_idx[j];
        float4 v = __ldg(X4 + s * 32 + lane);
        acc.x += v.x; acc.y += v.y; acc.z += v.z; acc.w += v.w;
    }
    float de = __ldg(degE + e);
    uint2 o;
    o.x = h2_to_u32(__floats2half2_rn(acc.x * de, acc.y * de));
    o.y = h2_to_u32(__floats2half2_rn(acc.z * de, acc.w * de));
    g_XeH[e * 32 + lane] = o;
}

// ---------------------------------------------------------------------------
// SpMM 2 + residual: XiH[v] = fp16( (1-a)*degV[v]*sum XeH[s] + a*X0[v] )
// ---------------------------------------------------------------------------
__global__ void spmm2_kernel(const float4* __restrict__ X04,
                             const float* __restrict__ degV,
                             const float* __restrict__ alpha) {
    int v = (blockIdx.x * blockDim.x + threadIdx.x) >> 5;
    if (v >= N_NODES) return;
    int lane = threadIdx.x & 31;
    int beg = g2_off[v], end = g2_off[v + 1];

    float4 acc = make_float4(0.f, 0.f, 0.f, 0.f);
    int j = beg;
    for (; j + 8 <= end; j += 8) {
        int s0 = g2_idx[j],     s1 = g2_idx[j + 1], s2 = g2_idx[j + 2], s3 = g2_idx[j + 3];
        int s4 = g2_idx[j + 4], s5 = g2_idx[j + 5], s6 = g2_idx[j + 6], s7 = g2_idx[j + 7];
        uint2 r0 = g_XeH[s0 * 32 + lane];
        uint2 r1 = g_XeH[s1 * 32 + lane];
        uint2 r2 = g_XeH[s2 * 32 + lane];
        uint2 r3 = g_XeH[s3 * 32 + lane];
        uint2 r4 = g_XeH[s4 * 32 + lane];
        uint2 r5 = g_XeH[s5 * 32 + lane];
        uint2 r6 = g_XeH[s6 * 32 + lane];
        uint2 r7 = g_XeH[s7 * 32 + lane];
        acc_h(acc, r0); acc_h(acc, r1); acc_h(acc, r2); acc_h(acc, r3);
        acc_h(acc, r4); acc_h(acc, r5); acc_h(acc, r6); acc_h(acc, r7);
    }
    for (; j + 4 <= end; j += 4) {
        int s0 = g2_idx[j], s1 = g2_idx[j + 1], s2 = g2_idx[j + 2], s3 = g2_idx[j + 3];
        uint2 r0 = g_XeH[s0 * 32 + lane];
        uint2 r1 = g_XeH[s1 * 32 + lane];
        uint2 r2 = g_XeH[s2 * 32 + lane];
        uint2 r3 = g_XeH[s3 * 32 + lane];
        acc_h(acc, r0); acc_h(acc, r1); acc_h(acc, r2); acc_h(acc, r3);
    }
    for (; j < end; j++) {
        int s = g2_idx[j];
        acc_h(acc, g_XeH[s * 32 + lane]);
    }
    float a = __ldg(alpha);
    float sc = (1.f - a) * __ldg(degV + v);
    float4 x0 = __ldg(X04 + v * 32 + lane);
    float xi0 = sc * acc.x + a * x0.x;
    float xi1 = sc * acc.y + a * x0.y;
    float xi2 = sc * acc.z + a * x0.z;
    float xi3 = sc * acc.w + a * x0.w;
    uint2 o;
    o.x = h2_to_u32(__floats2half2_rn(xi0, xi1));
    o.y = h2_to_u32(__floats2half2_rn(xi2, xi3));
    g_XiH[v * 32 + lane] = o;
}

// ---------------------------------------------------------------------------
// GEMM: out = (1-b)*Xi + b*(Xi @ W^T)   (Xi fp16 in g_XiH; exact 16-row tiling)
// ---------------------------------------------------------------------------
#define XI_STRIDE 132

__global__ void __launch_bounds__(256, 2)
gemm_kernel(const float* __restrict__ beta, float* __restrict__ out) {
    __shared__ float Xism[16 * XI_STRIDE];

    const int tid = threadIdx.x;
    const int row0 = blockIdx.x * 16;
    const float bb = __ldg(beta);
    const float omb = 1.f - bb;

    const int warp = tid >> 5, lane = tid & 31;
    const int gid = lane >> 2, tig = lane & 3;
    const int nt0 = warp, nt1 = warp + 8;

    float2 bf0[16], bf1[16];
#pragma unroll
    for (int kk = 0; kk < 16; kk++) {
        bf0[kk] = __ldg(&g_Wp[(kk * 4 + tig) * 128 + nt0 * 8 + gid]);
        bf1[kk] = __ldg(&g_Wp[(kk * 4 + tig) * 128 + nt1 * 8 + gid]);
    }

    // Stage Xi tile: fp16 global -> fp32 smem
#pragma unroll
    for (int i = tid; i < 16 * 32; i += 256) {
        int r = i >> 5, c4 = i & 31;
        uint2 h = g_XiH[(row0 + r) * 32 + c4];
        float2 f0 = __half22float2(u32_to_h2(h.x));
        float2 f1 = __half22float2(u32_to_h2(h.y));
        float4 xi = make_float4(f0.x, f0.y, f1.x, f1.y);
        *reinterpret_cast<float4*>(&Xism[r * XI_STRIDE + c4 * 4]) = xi;
    }
    __syncthreads();

    float c00 = 0.f, c01 = 0.f, c02 = 0.f, c03 = 0.f;
    float c10 = 0.f, c11 = 0.f, c12 = 0.f, c13 = 0.f;

#pragma unroll
    for (int kk = 0; kk < 16; kk++) {
        int c = kk * 8 + tig;
        uint32_t a0 = f2tf32(Xism[gid * XI_STRIDE + c]);
        uint32_t a1 = f2tf32(Xism[(gid + 8) * XI_STRIDE + c]);
        uint32_t a2 = f2tf32(Xism[gid * XI_STRIDE + c + 4]);
        uint32_t a3 = f2tf32(Xism[(gid + 8) * XI_STRIDE + c + 4]);
        uint32_t b00 = __float_as_uint(bf0[kk].x);
        uint32_t b01 = __float_as_uint(bf0[kk].y);
        uint32_t b10 = __float_as_uint(bf1[kk].x);
        uint32_t b11 = __float_as_uint(bf1[kk].y);
        asm volatile(
            "mma.sync.aligned.m16n8k8.row.col.f32.tf32.tf32.f32 "
            "{%0,%1,%2,%3}, {%4,%5,%6,%7}, {%8,%9}, {%0,%1,%2,%3};"
            : "+f"(c00), "+f"(c01), "+f"(c02), "+f"(c03)
            : "r"(a0), "r"(a1), "r"(a2), "r"(a3), "r"(b00), "r"(b01));
        asm volatile(
            "mma.sync.aligned.m16n8k8.row.col.f32.tf32.tf32.f32 "
            "{%0,%1,%2,%3}, {%4,%5,%6,%7}, {%8,%9}, {%0,%1,%2,%3};"
            : "+f"(c10), "+f"(c11), "+f"(c12), "+f"(c13)
            : "r"(a0), "r"(a1), "r"(a2), "r"(a3), "r"(b10), "r"(b11));
    }

    const int r0 = row0 + gid;
    const int r1 = r0 + 8;
    {
        int col = nt0 * 8 + 2 * tig;
        float xi0 = Xism[gid * XI_STRIDE + col];
        float xi1 = Xism[gid * XI_STRIDE + col + 1];
        *reinterpret_cast<float2*>(out + (long)r0 * 128 + col) =
            make_float2(omb * xi0 + bb * c00, omb * xi1 + bb * c01);
        xi0 = Xism[(gid + 8) * XI_STRIDE + col];
        xi1 = Xism[(gid + 8) * XI_STRIDE + col + 1];
        *reinterpret_cast<float2*>(out + (long)r1 * 128 + col) =
            make_float2(omb * xi0 + bb * c02, omb * xi1 + bb * c03);

        col = nt1 * 8 + 2 * tig;
        xi0 = Xism[gid * XI_STRIDE + col];
        xi1 = Xism[gid * XI_STRIDE + col + 1];
        *reinterpret_cast<float2*>(out + (long)r0 * 128 + col) =
            make_float2(omb * xi0 + bb * c10, omb * xi1 + bb * c11);
        xi0 = Xism[(gid + 8) * XI_STRIDE + col];
        xi1 = Xism[(gid + 8) * XI_STRIDE + col + 1];
        *reinterpret_cast<float2*>(out + (long)r1 * 128 + col) =
            make_float2(omb * xi0 + bb * c12, omb * xi1 + bb * c13);
    }
}

// ---------------------------------------------------------------------------
// kernel_launch — 5 launches (whole CSR build fused into one kernel)
// ---------------------------------------------------------------------------
extern "C" void kernel_launch(void* const* d_in, const int* in_sizes, int n_in,
                              void* d_out, int out_size) {
    const float* X     = (const float*)d_in[0];
    const float* X0    = (const float*)d_in[1];
    const float* degE  = (const float*)d_in[2];
    const float* degV  = (const float*)d_in[3];
    const float* alpha = (const float*)d_in[4];
    const float* beta  = (const float*)d_in[5];
    const float* W     = (const float*)d_in[6];
    const int*   g1s   = (const int*)d_in[7];
    const int*   g1d   = (const int*)d_in[8];
    const int*   g2s   = (const int*)d_in[9];
    const int*   g2d   = (const int*)d_in[10];
    float* out = (float*)d_out;

    // zero counters + barrier reset + W prep
    prep_kernel<<<ZERO_BLKS + WPREP_BLKS, 256>>>(W);

    // Fused CSR build: hist (+ranks) -> scan -> fill, one co-resident launch
    csr_kernel<<<MEGA_BLKS, 256>>>((const int4*)g1d, (const int4*)g2d,
                                   (const int2*)g1s, (const int2*)g1d,
                                   (const int2*)g2s, (const int2*)g2d);

    // Gather-sum SpMMs (fp32 X gather; fp16 Xe and Xi intermediates)
    spmm1_kernel<<<(N_EDGES * 32 + 255) / 256, 256>>>((const float4*)X, degE);
    spmm2_kernel<<<(N_NODES * 32 + 255) / 256, 256>>>((const float4*)X0, degV, alpha);

    // tf32 GEMM + residual epilogue (100000 = 6250 * 16 exact)
    gemm_kernel<<<N_NODES / 16, 256>>>(beta, out);
}

// round 16
// speedup vs baseline: 1.0309x; 1.0189x over previous
#include <cuda_runtime.h>
#include <cuda_fp16.h>
#include <cstdint>

#define N_NODES 100000
#define N_EDGES 20000
#define NNZ     800000
#define D       128

// Scan tiling
#define SCAN_TPB   256
#define SCAN_PER   8
#define SCAN_CHUNK (SCAN_TPB * SCAN_PER)                      // 2048
#define NB1 ((N_EDGES + SCAN_CHUNK - 1) / SCAN_CHUNK)         // 10
#define NB2 ((N_NODES + SCAN_CHUNK - 1) / SCAN_CHUNK)         // 49
#define NBT (NB1 + NB2)                                       // 59

typedef unsigned long long u64;

// ---------------------------------------------------------------------------
// Device-global scratch (allocation-free rule)
// ---------------------------------------------------------------------------
__device__ __align__(16) uint2 g_XeH[N_EDGES * 32]; // Xe fp16 (2x half2/lane), 5.12 MB
__device__ __align__(16) uint2 g_XiH[N_NODES * 32]; // Xi fp16, 25.6 MB
__device__ __align__(16) float2 g_Wp[64 * 128];     // packed tf32 B fragments, 64 KB

__device__ int g1_cnt[N_EDGES];
__device__ int g1_off[N_EDGES + 1];
__device__ int g1_idx[NNZ];
__device__ __align__(16) int g1_rank[NNZ];          // rank-within-destination
__device__ int g2_cnt[N_NODES];
__device__ int g2_off[N_NODES + 1];
__device__ int g2_idx[NNZ];
__device__ __align__(16) int g2_rank[NNZ];

__device__ int g_blk_sum[NBT];
__device__ int g_ready;            // reset by prep each replay

// ---------------------------------------------------------------------------
// helpers
// ---------------------------------------------------------------------------
__device__ __forceinline__ uint32_t h2_to_u32(__half2 h) {
    return *reinterpret_cast<uint32_t*>(&h);
}
__device__ __forceinline__ __half2 u32_to_h2(uint32_t u) {
    return *reinterpret_cast<__half2*>(&u);
}
__device__ __forceinline__ uint32_t f2tf32(float f) {
    uint32_t r;
    asm("cvt.rna.tf32.f32 %0, %1;" : "=r"(r) : "f"(f));
    return r;
}
// Packed dual-fp32 add (sm_103a): one instruction, two FADDs.
__device__ __forceinline__ u64 addx2(u64 a, u64 b) {
    u64 r;
    asm("add.rn.f32x2 %0, %1, %2;" : "=l"(r) : "l"(a), "l"(b));
    return r;
}
__device__ __forceinline__ float2 unpack64(u64 v) {
    float2 f;
    asm("mov.b64 {%0, %1}, %2;" : "=f"(f.x), "=f"(f.y) : "l"(v));
    return f;
}
// Convert half2 pair and accumulate into fp32 acc
__device__ __forceinline__ void acc_h2(float4& acc, __half2 hx, __half2 hy) {
    float2 f0 = __half22float2(hx);
    float2 f1 = __half22float2(hy);
    acc.x += f0.x; acc.y += f0.y; acc.z += f1.x; acc.w += f1.y;
}
__device__ __forceinline__ void acc_h(float4& acc, uint2 r) {
    acc_h2(acc, u32_to_h2(r.x), u32_to_h2(r.y));
}

// ---------------------------------------------------------------------------
// Prep: zero counters + ready flag (blocks 0..390) + W prep (391..422)
// ---------------------------------------------------------------------------
#define ZERO_BLKS ((N_NODES + 255) / 256)        // 391
#define WPREP_BLKS 32

__global__ void prep_kernel(const float* __restrict__ W) {
    if (blockIdx.x < ZERO_BLKS) {
        int i = blockIdx.x * blockDim.x + threadIdx.x;
        if (i < N_EDGES) g1_cnt[i] = 0;
        if (i < N_NODES) g2_cnt[i] = 0;
        if (i == 0) g_ready = 0;
    } else {
        int p = (blockIdx.x - ZERO_BLKS) * blockDim.x + threadIdx.x;  // 8192 total
        if (p < 64 * 128) {
            int n = p & 127;
            int tig = (p >> 7) & 3;
            int kk = p >> 9;
            float w0 = __ldg(W + n * 128 + kk * 8 + tig);
            float w1 = __ldg(W + n * 128 + kk * 8 + tig + 4);
            float2 o;
            o.x = __uint_as_float(f2tf32(w0));
            o.y = __uint_as_float(f2tf32(w1));
            g_Wp[p] = o;
        }
    }
}

// ---------------------------------------------------------------------------
// Histogram + rank recording, both graphs (int4-vectorized).
// ---------------------------------------------------------------------------
__global__ void hist_kernel(const int4* __restrict__ g1d4,
                            const int4* __restrict__ g2d4) {
    int i = blockIdx.x * blockDim.x + threadIdx.x;
    if (i >= NNZ / 4) return;
    int4 d1 = __ldg(g1d4 + i);
    int4 r1;
    r1.x = atomicAdd(&g1_cnt[d1.x], 1);
    r1.y = atomicAdd(&g1_cnt[d1.y], 1);
    r1.z = atomicAdd(&g1_cnt[d1.z], 1);
    r1.w = atomicAdd(&g1_cnt[d1.w], 1);
    reinterpret_cast<int4*>(g1_rank)[i] = r1;
    int4 d2 = __ldg(g2d4 + i);
    int4 r2;
    r2.x = atomicAdd(&g2_cnt[d2.x], 1);
    r2.y = atomicAdd(&g2_cnt[d2.y], 1);
    r2.z = atomicAdd(&g2_cnt[d2.z], 1);
    r2.w = atomicAdd(&g2_cnt[d2.w], 1);
    reinterpret_cast<int4*>(g2_rank)[i] = r2;
}

// ---------------------------------------------------------------------------
// Fused scan: single launch, 59 blocks (all co-resident; 59 < 148 SMs).
// ---------------------------------------------------------------------------
__global__ void scan_fused_kernel() {
    const int bid = blockIdx.x;
    const int t = threadIdx.x;
    const int* cnt; int* off; int n, lbase;
    if (bid < NB1) { cnt = g1_cnt; off = g1_off; n = N_EDGES; lbase = bid * SCAN_CHUNK; }
    else           { cnt = g2_cnt; off = g2_off; n = N_NODES; lbase = (bid - NB1) * SCAN_CHUNK; }

    int c[SCAN_PER];
    int s = 0;
    const int i0 = lbase + t * SCAN_PER;
#pragma unroll
    for (int k = 0; k < SCAN_PER; k++) {
        int i = i0 + k;
        c[k] = (i < n) ? cnt[i] : 0;
        s += c[k];
    }

    const int lane = t & 31, wid = t >> 5;
    int v = s;
#pragma unroll
    for (int o = 1; o < 32; o <<= 1) {
        int u = __shfl_up_sync(0xffffffffu, v, o);
        if (lane >= o) v += u;
    }
    __shared__ int ws[8];
    if (lane == 31) ws[wid] = v;
    __syncthreads();
    if (t < 8) {
        int w = ws[t];
#pragma unroll
        for (int o = 1; o < 8; o <<= 1) {
            int u = __shfl_up_sync(0xffu, w, o);
            if (t >= o) w += u;
        }
        ws[t] = w;
    }
    __syncthreads();

    int excl = v - s + (wid ? ws[wid - 1] : 0);
    if (t == SCAN_TPB - 1) {
        g_blk_sum[bid] = excl + s;
        __threadfence();
        atomicAdd(&g_ready, 1);
    }

    if (t == 0) {
        volatile int* rdy = &g_ready;
        while (*rdy < NBT) { }
    }
    __syncthreads();
    __threadfence();

    __shared__ int be[64];
    __shared__ int wtot;
    if (t < 64) {
        int bv = (t < NBT) ? g_blk_sum[t] : 0;
        int bs = bv;
#pragma unroll
        for (int o = 1; o < 32; o <<= 1) {
            int u = __shfl_up_sync(0xffffffffu, bs, o);
            if ((t & 31) >= o) bs += u;
        }
        if (t == 31) wtot = bs;
        be[t] = bs - bv;
    }
    __syncthreads();
    if (t >= 32 && t < 64) be[t] += wtot;
    __syncthreads();

    int base = be[bid] + excl;
    if (bid >= NB1) base -= NNZ;
#pragma unroll
    for (int k = 0; k < SCAN_PER; k++) {
        int i = i0 + k;
        if (i < n) {
            off[i] = base;
            base += c[k];
        }
    }
    if (bid == 0 && t == 0) {
        g1_off[N_EDGES] = NNZ;
        g2_off[N_NODES] = NNZ;
    }
}

// ---------------------------------------------------------------------------
// Fill — atomic-free, 2 nnz/thread/graph (R13 layout: best measured)
// ---------------------------------------------------------------------------
__global__ void fill_kernel(const int2* __restrict__ g1s2, const int2* __restrict__ g1d2,
                            const int2* __restrict__ g2s2, const int2* __restrict__ g2d2) {
    int i = blockIdx.x * blockDim.x + threadIdx.x;
    if (i >= NNZ / 2) return;
    int2 s1 = __ldg(g1s2 + i);
    int2 d1 = __ldg(g1d2 + i);
    int2 r1 = *reinterpret_cast<const int2*>(g1_rank + 2 * i);
    g1_idx[g1_off[d1.x] + r1.x] = s1.x;
    g1_idx[g1_off[d1.y] + r1.y] = s1.y;
    int2 s2 = __ldg(g2s2 + i);
    int2 d2 = __ldg(g2d2 + i);
    int2 r2 = *reinterpret_cast<const int2*>(g2_rank + 2 * i);
    g2_idx[g2_off[d2.x] + r2.x] = s2.x;
    g2_idx[g2_off[d2.y] + r2.y] = s2.y;
}

// ---------------------------------------------------------------------------
// SpMM 1: XeH[e] = fp16( degE[e] * sum X[s] )
// fp32 gather as ulonglong2 + packed add.rn.f32x2 tree (halved FADD issue)
// ---------------------------------------------------------------------------
__global__ void spmm1_kernel(const ulonglong2* __restrict__ X2,
                             const float* __restrict__ degE) {
    int e = (blockIdx.x * blockDim.x + threadIdx.x) >> 5;
    if (e >= N_EDGES) return;
    int lane = threadIdx.x & 31;
    int beg = g1_off[e], end = g1_off[e + 1];

    u64 a0 = 0ull, a1 = 0ull;      // packed {f32,f32} accumulators (0.0,0.0)
    int j = beg;
    for (; j + 8 <= end; j += 8) {
        int s0 = g1_idx[j],     s1 = g1_idx[j + 1], s2 = g1_idx[j + 2], s3 = g1_idx[j + 3];
        int s4 = g1_idx[j + 4], s5 = g1_idx[j + 5], s6 = g1_idx[j + 6], s7 = g1_idx[j + 7];
        ulonglong2 v0 = __ldg(X2 + s0 * 32 + lane);
        ulonglong2 v1 = __ldg(X2 + s1 * 32 + lane);
        ulonglong2 v2 = __ldg(X2 + s2 * 32 + lane);
        ulonglong2 v3 = __ldg(X2 + s3 * 32 + lane);
        ulonglong2 v4 = __ldg(X2 + s4 * 32 + lane);
        ulonglong2 v5 = __ldg(X2 + s5 * 32 + lane);
        ulonglong2 v6 = __ldg(X2 + s6 * 32 + lane);
        ulonglong2 v7 = __ldg(X2 + s7 * 32 + lane);
        u64 t0 = addx2(addx2(v0.x, v1.x), addx2(v2.x, v3.x));
        u64 t1 = addx2(addx2(v4.x, v5.x), addx2(v6.x, v7.x));
        a0 = addx2(a0, addx2(t0, t1));
        u64 t2 = addx2(addx2(v0.y, v1.y), addx2(v2.y, v3.y));
        u64 t3 = addx2(addx2(v4.y, v5.y), addx2(v6.y, v7.y));
        a1 = addx2(a1, addx2(t2, t3));
    }
    for (; j < end; j++) {
        int s = g1_idx[j];
        ulonglong2 v = __ldg(X2 + s * 32 + lane);
        a0 = addx2(a0, v.x);
        a1 = addx2(a1, v.y);
    }
    float2 f0 = unpack64(a0);
    float2 f1 = unpack64(a1);
    float de = __ldg(degE + e);
    uint2 o;
    o.x = h2_to_u32(__floats2half2_rn(f0.x * de, f0.y * de));
    o.y = h2_to_u32(__floats2half2_rn(f1.x * de, f1.y * de));
    g_XeH[e * 32 + lane] = o;
}

// ---------------------------------------------------------------------------
// SpMM 2 + residual: XiH[v] = fp16( (1-a)*degV[v]*sum XeH[s] + a*X0[v] )
// One-level fp16 pairing (__hadd2) before fp32 convert/accumulate:
// per 8 rows: 8 HADD2 + 16 CVT + 16 FADD  (was 32 CVT + 32 FADD)
// ---------------------------------------------------------------------------
__global__ void spmm2_kernel(const float4* __restrict__ X04,
                             const float* __restrict__ degV,
                             const float* __restrict__ alpha) {
    int v = (blockIdx.x * blockDim.x + threadIdx.x) >> 5;
    if (v >= N_NODES) return;
    int lane = threadIdx.x & 31;
    int beg = g2_off[v], end = g2_off[v + 1];

    float4 acc = make_float4(0.f, 0.f, 0.f, 0.f);
    int j = beg;
    for (; j + 8 <= end; j += 8) {
        int s0 = g2_idx[j],     s1 = g2_idx[j + 1], s2 = g2_idx[j + 2], s3 = g2_idx[j + 3];
        int s4 = g2_idx[j + 4], s5 = g2_idx[j + 5], s6 = g2_idx[j + 6], s7 = g2_idx[j + 7];
        uint2 r0 = g_XeH[s0 * 32 + lane];
        uint2 r1 = g_XeH[s1 * 32 + lane];
        uint2 r2 = g_XeH[s2 * 32 + lane];
        uint2 r3 = g_XeH[s3 * 32 + lane];
        uint2 r4 = g_XeH[s4 * 32 + lane];
        uint2 r5 = g_XeH[s5 * 32 + lane];
        uint2 r6 = g_XeH[s6 * 32 + lane];
        uint2 r7 = g_XeH[s7 * 32 + lane];
        acc_h2(acc, __hadd2(u32_to_h2(r0.x), u32_to_h2(r1.x)),
                     __hadd2(u32_to_h2(r0.y), u32_to_h2(r1.y)));
        acc_h2(acc, __hadd2(u32_to_h2(r2.x), u32_to_h2(r3.x)),
                     __hadd2(u32_to_h2(r2.y), u32_to_h2(r3.y)));
        acc_h2(acc, __hadd2(u32_to_h2(r4.x), u32_to_h2(r5.x)),
                     __hadd2(u32_to_h2(r4.y), u32_to_h2(r5.y)));
        acc_h2(acc, __hadd2(u32_to_h2(r6.x), u32_to_h2(r7.x)),
                     __hadd2(u32_to_h2(r6.y), u32_to_h2(r7.y)));
    }
    for (; j + 2 <= end; j += 2) {
        int s0 = g2_idx[j], s1 = g2_idx[j + 1];
        uint2 r0 = g_XeH[s0 * 32 + lane];
        uint2 r1 = g_XeH[s1 * 32 + lane];
        acc_h2(acc, __hadd2(u32_to_h2(r0.x), u32_to_h2(r1.x)),
                     __hadd2(u32_to_h2(r0.y), u32_to_h2(r1.y)));
    }
    if (j < end) {
        int s = g2_idx[j];
        acc_h(acc, g_XeH[s * 32 + lane]);
    }
    float a = __ldg(alpha);
    float sc = (1.f - a) * __ldg(degV + v);
    float4 x0 = __ldg(X04 + v * 32 + lane);
    float xi0 = sc * acc.x + a * x0.x;
    float xi1 = sc * acc.y + a * x0.y;
    float xi2 = sc * acc.z + a * x0.z;
    float xi3 = sc * acc.w + a * x0.w;
    uint2 o;
    o.x = h2_to_u32(__floats2half2_rn(xi0, xi1));
    o.y = h2_to_u32(__floats2half2_rn(xi2, xi3));
    g_XiH[v * 32 + lane] = o;
}

// ---------------------------------------------------------------------------
// GEMM: out = (1-b)*Xi + b*(Xi @ W^T)   (Xi fp16 in g_XiH; exact 16-row tiling)
// ---------------------------------------------------------------------------
#define XI_STRIDE 132

__global__ void __launch_bounds__(256, 2)
gemm_kernel(const float* __restrict__ beta, float* __restrict__ out) {
    __shared__ float Xism[16 * XI_STRIDE];

    const int tid = threadIdx.x;
    const int row0 = blockIdx.x * 16;
    const float bb = __ldg(beta);
    const float omb = 1.f - bb;

    const int warp = tid >> 5, lane = tid & 31;
    const int gid = lane >> 2, tig = lane & 3;
    const int nt0 = warp, nt1 = warp + 8;

    float2 bf0[16], bf1[16];
#pragma unroll
    for (int kk = 0; kk < 16; kk++) {
        bf0[kk] = __ldg(&g_Wp[(kk * 4 + tig) * 128 + nt0 * 8 + gid]);
        bf1[kk] = __ldg(&g_Wp[(kk * 4 + tig) * 128 + nt1 * 8 + gid]);
    }

    // Stage Xi tile: fp16 global -> fp32 smem
#pragma unroll
    for (int i = tid; i < 16 * 32; i += 256) {
        int r = i >> 5, c4 = i & 31;
        uint2 h = g_XiH[(row0 + r) * 32 + c4];
        float2 f0 = __half22float2(u32_to_h2(h.x));
        float2 f1 = __half22float2(u32_to_h2(h.y));
        float4 xi = make_float4(f0.x, f0.y, f1.x, f1.y);
        *reinterpret_cast<float4*>(&Xism[r * XI_STRIDE + c4 * 4]) = xi;
    }
    __syncthreads();

    float c00 = 0.f, c01 = 0.f, c02 = 0.f, c03 = 0.f;
    float c10 = 0.f, c11 = 0.f, c12 = 0.f, c13 = 0.f;

#pragma unroll
    for (int kk = 0; kk < 16; kk++) {
        int c = kk * 8 + tig;
        uint32_t a0 = f2tf32(Xism[gid * XI_STRIDE + c]);
        uint32_t a1 = f2tf32(Xism[(gid + 8) * XI_STRIDE + c]);
        uint32_t a2 = f2tf32(Xism[gid * XI_STRIDE + c + 4]);
        uint32_t a3 = f2tf32(Xism[(gid + 8) * XI_STRIDE + c + 4]);
        uint32_t b00 = __float_as_uint(bf0[kk].x);
        uint32_t b01 = __float_as_uint(bf0[kk].y);
        uint32_t b10 = __float_as_uint(bf1[kk].x);
        uint32_t b11 = __float_as_uint(bf1[kk].y);
        asm volatile(
            "mma.sync.aligned.m16n8k8.row.col.f32.tf32.tf32.f32 "
            "{%0,%1,%2,%3}, {%4,%5,%6,%7}, {%8,%9}, {%0,%1,%2,%3};"
            : "+f"(c00), "+f"(c01), "+f"(c02), "+f"(c03)
            : "r"(a0), "r"(a1), "r"(a2), "r"(a3), "r"(b00), "r"(b01));
        asm volatile(
            "mma.sync.aligned.m16n8k8.row.col.f32.tf32.tf32.f32 "
            "{%0,%1,%2,%3}, {%4,%5,%6,%7}, {%8,%9}, {%0,%1,%2,%3};"
            : "+f"(c10), "+f"(c11), "+f"(c12), "+f"(c13)
            : "r"(a0), "r"(a1), "r"(a2), "r"(a3), "r"(b10), "r"(b11));
    }

    const int r0 = row0 + gid;
    const int r1 = r0 + 8;
    {
        int col = nt0 * 8 + 2 * tig;
        float xi0 = Xism[gid * XI_STRIDE + col];
        float xi1 = Xism[gid * XI_STRIDE + col + 1];
        *reinterpret_cast<float2*>(out + (long)r0 * 128 + col) =
            make_float2(omb * xi0 + bb * c00, omb * xi1 + bb * c01);
        xi0 = Xism[(gid + 8) * XI_STRIDE + col];
        xi1 = Xism[(gid + 8) * XI_STRIDE + col + 1];
        *reinterpret_cast<float2*>(out + (long)r1 * 128 + col) =
            make_float2(omb * xi0 + bb * c02, omb * xi1 + bb * c03);

        col = nt1 * 8 + 2 * tig;
        xi0 = Xism[gid * XI_STRIDE + col];
        xi1 = Xism[gid * XI_STRIDE + col + 1];
        *reinterpret_cast<float2*>(out + (long)r0 * 128 + col) =
            make_float2(omb * xi0 + bb * c10, omb * xi1 + bb * c11);
        xi0 = Xism[(gid + 8) * XI_STRIDE + col];
        xi1 = Xism[(gid + 8) * XI_STRIDE + col + 1];
        *reinterpret_cast<float2*>(out + (long)r1 * 128 + col) =
            make_float2(omb * xi0 + bb * c12, omb * xi1 + bb * c13);
    }
}

// ---------------------------------------------------------------------------
// kernel_launch — R13 structure (best) + issue-optimized spmm kernels
// ---------------------------------------------------------------------------
extern "C" void kernel_launch(void* const* d_in, const int* in_sizes, int n_in,
                              void* d_out, int out_size) {
    const float* X     = (const float*)d_in[0];
    const float* X0    = (const float*)d_in[1];
    const float* degE  = (const float*)d_in[2];
    const float* degV  = (const float*)d_in[3];
    const float* alpha = (const float*)d_in[4];
    const float* beta  = (const float*)d_in[5];
    const float* W     = (const float*)d_in[6];
    const int*   g1s   = (const int*)d_in[7];
    const int*   g1d   = (const int*)d_in[8];
    const int*   g2s   = (const int*)d_in[9];
    const int*   g2d   = (const int*)d_in[10];
    float* out = (float*)d_out;

    // zero counters + ready flag + W prep
    prep_kernel<<<ZERO_BLKS + WPREP_BLKS, 256>>>(W);

    // CSR build: rank-recording hist -> fused scan -> atomic-free fill
    hist_kernel<<<(NNZ / 4 + 255) / 256, 256>>>((const int4*)g1d, (const int4*)g2d);
    scan_fused_kernel<<<NBT, SCAN_TPB>>>();
    fill_kernel<<<(NNZ / 2 + 255) / 256, 256>>>((const int2*)g1s, (const int2*)g1d,
                                                (const int2*)g2s, (const int2*)g2d);

    // Gather-sum SpMMs: packed f32x2 tree (spmm1), fp16-paired converts (spmm2)
    spmm1_kernel<<<(N_EDGES * 32 + 255) / 256, 256>>>((const ulonglong2*)X, degE);
    spmm2_kernel<<<(N_NODES * 32 + 255) / 256, 256>>>((const float4*)X0, degV, alpha);

    // tf32 GEMM + residual epilogue (100000 = 6250 * 16 exact)
    gemm_kernel<<<N_NODES / 16, 256>>>(beta, out);
}

// round 17
// speedup vs baseline: 1.0598x; 1.0280x over previous
#include <cuda_runtime.h>
#include <cuda_fp16.h>
#include <cstdint>

#define N_NODES 100000
#define N_EDGES 20000
#define NNZ     800000
#define D       128

// Scan tiling
#define SCAN_TPB   256
#define SCAN_PER   8
#define SCAN_CHUNK (SCAN_TPB * SCAN_PER)                      // 2048
#define NB1 ((N_EDGES + SCAN_CHUNK - 1) / SCAN_CHUNK)         // 10
#define NB2 ((N_NODES + SCAN_CHUNK - 1) / SCAN_CHUNK)         // 49
#define NBT (NB1 + NB2)                                       // 59

// ---------------------------------------------------------------------------
// Device-global scratch (allocation-free rule)
// ---------------------------------------------------------------------------
__device__ __align__(16) uint2 g_XH [N_NODES * 32]; // X fp16 (2x half2/lane), 25.6 MB
__device__ __align__(16) uint2 g_XeH[N_EDGES * 32]; // Xe fp16, 5.12 MB
__device__ __align__(16) uint2 g_XiH[N_NODES * 32]; // Xi fp16, 25.6 MB
__device__ __align__(16) float2 g_Wp[64 * 128];     // packed tf32 B fragments, 64 KB

__device__ int g1_cnt[N_EDGES];
__device__ int g1_off[N_EDGES + 1];
__device__ int g1_idx[NNZ];
__device__ __align__(16) int g1_rank[NNZ];          // rank-within-destination
__device__ int g2_cnt[N_NODES];
__device__ int g2_off[N_NODES + 1];
__device__ int g2_idx[NNZ];
__device__ __align__(16) int g2_rank[NNZ];

__device__ int g_blk_sum[NBT];
__device__ int g_ready;            // reset by prep each replay

// ---------------------------------------------------------------------------
// helpers
// ---------------------------------------------------------------------------
__device__ __forceinline__ uint32_t h2_to_u32(__half2 h) {
    return *reinterpret_cast<uint32_t*>(&h);
}
__device__ __forceinline__ __half2 u32_to_h2(uint32_t u) {
    return *reinterpret_cast<__half2*>(&u);
}
__device__ __forceinline__ uint32_t f2tf32(float f) {
    uint32_t r;
    asm("cvt.rna.tf32.f32 %0, %1;" : "=r"(r) : "f"(f));
    return r;
}
// Convert half2 pair and accumulate into fp32 acc
__device__ __forceinline__ void acc_h2(float4& acc, __half2 hx, __half2 hy) {
    float2 f0 = __half22float2(hx);
    float2 f1 = __half22float2(hy);
    acc.x += f0.x; acc.y += f0.y; acc.z += f1.x; acc.w += f1.y;
}
__device__ __forceinline__ void acc_h(float4& acc, uint2 r) {
    acc_h2(acc, u32_to_h2(r.x), u32_to_h2(r.y));
}

// ---------------------------------------------------------------------------
// Prep: zero counters + ready flag (blocks 0..390) + W prep (391..422)
// ---------------------------------------------------------------------------
#define ZERO_BLKS ((N_NODES + 255) / 256)        // 391
#define WPREP_BLKS 32

__global__ void prep_kernel(const float* __restrict__ W) {
    if (blockIdx.x < ZERO_BLKS) {
        int i = blockIdx.x * blockDim.x + threadIdx.x;
        if (i < N_EDGES) g1_cnt[i] = 0;
        if (i < N_NODES) g2_cnt[i] = 0;
        if (i == 0) g_ready = 0;
    } else {
        int p = (blockIdx.x - ZERO_BLKS) * blockDim.x + threadIdx.x;  // 8192 total
        if (p < 64 * 128) {
            int n = p & 127;
            int tig = (p >> 7) & 3;
            int kk = p >> 9;
            float w0 = __ldg(W + n * 128 + kk * 8 + tig);
            float w1 = __ldg(W + n * 128 + kk * 8 + tig + 4);
            float2 o;
            o.x = __uint_as_float(f2tf32(w0));
            o.y = __uint_as_float(f2tf32(w1));
            g_Wp[p] = o;
        }
    }
}

// ---------------------------------------------------------------------------
// Histogram + rank recording, both graphs (int4-vectorized).
// ---------------------------------------------------------------------------
__global__ void hist_kernel(const int4* __restrict__ g1d4,
                            const int4* __restrict__ g2d4) {
    int i = blockIdx.x * blockDim.x + threadIdx.x;
    if (i >= NNZ / 4) return;
    int4 d1 = __ldg(g1d4 + i);
    int4 r1;
    r1.x = atomicAdd(&g1_cnt[d1.x], 1);
    r1.y = atomicAdd(&g1_cnt[d1.y], 1);
    r1.z = atomicAdd(&g1_cnt[d1.z], 1);
    r1.w = atomicAdd(&g1_cnt[d1.w], 1);
    reinterpret_cast<int4*>(g1_rank)[i] = r1;
    int4 d2 = __ldg(g2d4 + i);
    int4 r2;
    r2.x = atomicAdd(&g2_cnt[d2.x], 1);
    r2.y = atomicAdd(&g2_cnt[d2.y], 1);
    r2.z = atomicAdd(&g2_cnt[d2.z], 1);
    r2.w = atomicAdd(&g2_cnt[d2.w], 1);
    reinterpret_cast<int4*>(g2_rank)[i] = r2;
}

// ---------------------------------------------------------------------------
// Fused scan: single launch, 59 blocks (all co-resident; 59 < 148 SMs).
// ---------------------------------------------------------------------------
__global__ void scan_fused_kernel() {
    const int bid = blockIdx.x;
    const int t = threadIdx.x;
    const int* cnt; int* off; int n, lbase;
    if (bid < NB1) { cnt = g1_cnt; off = g1_off; n = N_EDGES; lbase = bid * SCAN_CHUNK; }
    else           { cnt = g2_cnt; off = g2_off; n = N_NODES; lbase = (bid - NB1) * SCAN_CHUNK; }

    int c[SCAN_PER];
    int s = 0;
    const int i0 = lbase + t * SCAN_PER;
#pragma unroll
    for (int k = 0; k < SCAN_PER; k++) {
        int i = i0 + k;
        c[k] = (i < n) ? cnt[i] : 0;
        s += c[k];
    }

    const int lane = t & 31, wid = t >> 5;
    int v = s;
#pragma unroll
    for (int o = 1; o < 32; o <<= 1) {
        int u = __shfl_up_sync(0xffffffffu, v, o);
        if (lane >= o) v += u;
    }
    __shared__ int ws[8];
    if (lane == 31) ws[wid] = v;
    __syncthreads();
    if (t < 8) {
        int w = ws[t];
#pragma unroll
        for (int o = 1; o < 8; o <<= 1) {
            int u = __shfl_up_sync(0xffu, w, o);
            if (t >= o) w += u;
        }
        ws[t] = w;
    }
    __syncthreads();

    int excl = v - s + (wid ? ws[wid - 1] : 0);
    if (t == SCAN_TPB - 1) {
        g_blk_sum[bid] = excl + s;
        __threadfence();
        atomicAdd(&g_ready, 1);
    }

    if (t == 0) {
        volatile int* rdy = &g_ready;
        while (*rdy < NBT) { }
    }
    __syncthreads();
    __threadfence();

    __shared__ int be[64];
    __shared__ int wtot;
    if (t < 64) {
        int bv = (t < NBT) ? g_blk_sum[t] : 0;
        int bs = bv;
#pragma unroll
        for (int o = 1; o < 32; o <<= 1) {
            int u = __shfl_up_sync(0xffffffffu, bs, o);
            if ((t & 31) >= o) bs += u;
        }
        if (t == 31) wtot = bs;
        be[t] = bs - bv;
    }
    __syncthreads();
    if (t >= 32 && t < 64) be[t] += wtot;
    __syncthreads();

    int base = be[bid] + excl;
    if (bid >= NB1) base -= NNZ;
#pragma unroll
    for (int k = 0; k < SCAN_PER; k++) {
        int i = i0 + k;
        if (i < n) {
            off[i] = base;
            base += c[k];
        }
    }
    if (bid == 0 && t == 0) {
        g1_off[N_EDGES] = NNZ;
        g2_off[N_NODES] = NNZ;
    }
}

// ---------------------------------------------------------------------------
// Fill — atomic-free (R13 layout) + X->fp16 conversion hidden in its
// scoreboard-stall shadow (fill: issue 4%, DRAM 14% — idle resources).
// ---------------------------------------------------------------------------
#define FILL_BLKS ((NNZ / 2 + 255) / 256)   // 1563

__global__ void fill_kernel(const int2* __restrict__ g1s2, const int2* __restrict__ g1d2,
                            const int2* __restrict__ g2s2, const int2* __restrict__ g2d2,
                            const float4* __restrict__ X4) {
    int i = blockIdx.x * blockDim.x + threadIdx.x;
    if (i < NNZ / 2) {
        int2 s1 = __ldg(g1s2 + i);
        int2 d1 = __ldg(g1d2 + i);
        int2 r1 = *reinterpret_cast<const int2*>(g1_rank + 2 * i);
        g1_idx[g1_off[d1.x] + r1.x] = s1.x;
        g1_idx[g1_off[d1.y] + r1.y] = s1.y;
        int2 s2 = __ldg(g2s2 + i);
        int2 d2 = __ldg(g2d2 + i);
        int2 r2 = *reinterpret_cast<const int2*>(g2_rank + 2 * i);
        g2_idx[g2_off[d2.x] + r2.x] = s2.x;
        g2_idx[g2_off[d2.y] + r2.y] = s2.y;
    }
    // X -> fp16 (3.2M float4 granules, 8 per thread), overlaps stall shadow
    const int nthr = FILL_BLKS * 256;
    for (int j = i; j < N_NODES * 32; j += nthr) {
        float4 v = __ldg(X4 + j);
        uint2 o;
        o.x = h2_to_u32(__floats2half2_rn(v.x, v.y));
        o.y = h2_to_u32(__floats2half2_rn(v.z, v.w));
        g_XH[j] = o;
    }
}

// ---------------------------------------------------------------------------
// SpMM 1: XeH[e] = fp16( degE[e] * sum XH[s] )
// fp16 gather (8B/lane), one-level __hadd2 pairing, fp32 accumulate
// ---------------------------------------------------------------------------
__global__ void spmm1_kernel(const float* __restrict__ degE) {
    int e = (blockIdx.x * blockDim.x + threadIdx.x) >> 5;
    if (e >= N_EDGES) return;
    int lane = threadIdx.x & 31;
    int beg = g1_off[e], end = g1_off[e + 1];

    float4 acc = make_float4(0.f, 0.f, 0.f, 0.f);
    int j = beg;
    for (; j + 8 <= end; j += 8) {
        int s0 = g1_idx[j],     s1 = g1_idx[j + 1], s2 = g1_idx[j + 2], s3 = g1_idx[j + 3];
        int s4 = g1_idx[j + 4], s5 = g1_idx[j + 5], s6 = g1_idx[j + 6], s7 = g1_idx[j + 7];
        uint2 r0 = g_XH[s0 * 32 + lane];
        uint2 r1 = g_XH[s1 * 32 + lane];
        uint2 r2 = g_XH[s2 * 32 + lane];
        uint2 r3 = g_XH[s3 * 32 + lane];
        uint2 r4 = g_XH[s4 * 32 + lane];
        uint2 r5 = g_XH[s5 * 32 + lane];
        uint2 r6 = g_XH[s6 * 32 + lane];
        uint2 r7 = g_XH[s7 * 32 + lane];
        acc_h2(acc, __hadd2(u32_to_h2(r0.x), u32_to_h2(r1.x)),
                     __hadd2(u32_to_h2(r0.y), u32_to_h2(r1.y)));
        acc_h2(acc, __hadd2(u32_to_h2(r2.x), u32_to_h2(r3.x)),
                     __hadd2(u32_to_h2(r2.y), u32_to_h2(r3.y)));
        acc_h2(acc, __hadd2(u32_to_h2(r4.x), u32_to_h2(r5.x)),
                     __hadd2(u32_to_h2(r4.y), u32_to_h2(r5.y)));
        acc_h2(acc, __hadd2(u32_to_h2(r6.x), u32_to_h2(r7.x)),
                     __hadd2(u32_to_h2(r6.y), u32_to_h2(r7.y)));
    }
    for (; j + 2 <= end; j += 2) {
        int s0 = g1_idx[j], s1 = g1_idx[j + 1];
        uint2 r0 = g_XH[s0 * 32 + lane];
        uint2 r1 = g_XH[s1 * 32 + lane];
        acc_h2(acc, __hadd2(u32_to_h2(r0.x), u32_to_h2(r1.x)),
                     __hadd2(u32_to_h2(r0.y), u32_to_h2(r1.y)));
    }
    if (j < end) {
        int s = g1_idx[j];
        acc_h(acc, g_XH[s * 32 + lane]);
    }
    float de = __ldg(degE + e);
    uint2 o;
    o.x = h2_to_u32(__floats2half2_rn(acc.x * de, acc.y * de));
    o.y = h2_to_u32(__floats2half2_rn(acc.z * de, acc.w * de));
    g_XeH[e * 32 + lane] = o;
}

// ---------------------------------------------------------------------------
// SpMM 2 + residual: XiH[v] = fp16( (1-a)*degV[v]*sum XeH[s] + a*X0[v] )
// Two-level fp16 pairing: per 8 rows 12 HADD2 + 4 CVT + 8 FADD
// ---------------------------------------------------------------------------
__global__ void spmm2_kernel(const float4* __restrict__ X04,
                             const float* __restrict__ degV,
                             const float* __restrict__ alpha) {
    int v = (blockIdx.x * blockDim.x + threadIdx.x) >> 5;
    if (v >= N_NODES) return;
    int lane = threadIdx.x & 31;
    int beg = g2_off[v], end = g2_off[v + 1];

    float4 acc = make_float4(0.f, 0.f, 0.f, 0.f);
    int j = beg;
    for (; j + 8 <= end; j += 8) {
        int s0 = g2_idx[j],     s1 = g2_idx[j + 1], s2 = g2_idx[j + 2], s3 = g2_idx[j + 3];
        int s4 = g2_idx[j + 4], s5 = g2_idx[j + 5], s6 = g2_idx[j + 6], s7 = g2_idx[j + 7];
        uint2 r0 = g_XeH[s0 * 32 + lane];
        uint2 r1 = g_XeH[s1 * 32 + lane];
        uint2 r2 = g_XeH[s2 * 32 + lane];
        uint2 r3 = g_XeH[s3 * 32 + lane];
        uint2 r4 = g_XeH[s4 * 32 + lane];
        uint2 r5 = g_XeH[s5 * 32 + lane];
        uint2 r6 = g_XeH[s6 * 32 + lane];
        uint2 r7 = g_XeH[s7 * 32 + lane];
        __half2 ax = __hadd2(__hadd2(u32_to_h2(r0.x), u32_to_h2(r1.x)),
                             __hadd2(u32_to_h2(r2.x), u32_to_h2(r3.x)));
        __half2 ay = __hadd2(__hadd2(u32_to_h2(r0.y), u32_to_h2(r1.y)),
                             __hadd2(u32_to_h2(r2.y), u32_to_h2(r3.y)));
        acc_h2(acc, ax, ay);
        __half2 bx = __hadd2(__hadd2(u32_to_h2(r4.x), u32_to_h2(r5.x)),
                             __hadd2(u32_to_h2(r6.x), u32_to_h2(r7.x)));
        __half2 by = __hadd2(__hadd2(u32_to_h2(r4.y), u32_to_h2(r5.y)),
                             __hadd2(u32_to_h2(r6.y), u32_to_h2(r7.y)));
        acc_h2(acc, bx, by);
    }
    for (; j + 2 <= end; j += 2) {
        int s0 = g2_idx[j], s1 = g2_idx[j + 1];
        uint2 r0 = g_XeH[s0 * 32 + lane];
        uint2 r1 = g_XeH[s1 * 32 + lane];
        acc_h2(acc, __hadd2(u32_to_h2(r0.x), u32_to_h2(r1.x)),
                     __hadd2(u32_to_h2(r0.y), u32_to_h2(r1.y)));
    }
    if (j < end) {
        int s = g2_idx[j];
        acc_h(acc, g_XeH[s * 32 + lane]);
    }
    float a = __ldg(alpha);
    float sc = (1.f - a) * __ldg(degV + v);
    float4 x0 = __ldg(X04 + v * 32 + lane);
    float xi0 = sc * acc.x + a * x0.x;
    float xi1 = sc * acc.y + a * x0.y;
    float xi2 = sc * acc.z + a * x0.z;
    float xi3 = sc * acc.w + a * x0.w;
    uint2 o;
    o.x = h2_to_u32(__floats2half2_rn(xi0, xi1));
    o.y = h2_to_u32(__floats2half2_rn(xi2, xi3));
    g_XiH[v * 32 + lane] = o;
}

// ---------------------------------------------------------------------------
// GEMM: out = (1-b)*Xi + b*(Xi @ W^T)   (Xi fp16 in g_XiH; exact 16-row tiling)
// ---------------------------------------------------------------------------
#define XI_STRIDE 132

__global__ void __launch_bounds__(256, 2)
gemm_kernel(const float* __restrict__ beta, float* __restrict__ out) {
    __shared__ float Xism[16 * XI_STRIDE];

    const int tid = threadIdx.x;
    const int row0 = blockIdx.x * 16;
    const float bb = __ldg(beta);
    const float omb = 1.f - bb;

    const int warp = tid >> 5, lane = tid & 31;
    const int gid = lane >> 2, tig = lane & 3;
    const int nt0 = warp, nt1 = warp + 8;

    float2 bf0[16], bf1[16];
#pragma unroll
    for (int kk = 0; kk < 16; kk++) {
        bf0[kk] = __ldg(&g_Wp[(kk * 4 + tig) * 128 + nt0 * 8 + gid]);
        bf1[kk] = __ldg(&g_Wp[(kk * 4 + tig) * 128 + nt1 * 8 + gid]);
    }

    // Stage Xi tile: fp16 global -> fp32 smem
#pragma unroll
    for (int i = tid; i < 16 * 32; i += 256) {
        int r = i >> 5, c4 = i & 31;
        uint2 h = g_XiH[(row0 + r) * 32 + c4];
        float2 f0 = __half22float2(u32_to_h2(h.x));
        float2 f1 = __half22float2(u32_to_h2(h.y));
        float4 xi = make_float4(f0.x, f0.y, f1.x, f1.y);
        *reinterpret_cast<float4*>(&Xism[r * XI_STRIDE + c4 * 4]) = xi;
    }
    __syncthreads();

    float c00 = 0.f, c01 = 0.f, c02 = 0.f, c03 = 0.f;
    float c10 = 0.f, c11 = 0.f, c12 = 0.f, c13 = 0.f;

#pragma unroll
    for (int kk = 0; kk < 16; kk++) {
        int c = kk * 8 + tig;
        uint32_t a0 = f2tf32(Xism[gid * XI_STRIDE + c]);
        uint32_t a1 = f2tf32(Xism[(gid + 8) * XI_STRIDE + c]);
        uint32_t a2 = f2tf32(Xism[gid * XI_STRIDE + c + 4]);
        uint32_t a3 = f2tf32(Xism[(gid + 8) * XI_STRIDE + c + 4]);
        uint32_t b00 = __float_as_uint(bf0[kk].x);
        uint32_t b01 = __float_as_uint(bf0[kk].y);
        uint32_t b10 = __float_as_uint(bf1[kk].x);
        uint32_t b11 = __float_as_uint(bf1[kk].y);
        asm volatile(
            "mma.sync.aligned.m16n8k8.row.col.f32.tf32.tf32.f32 "
            "{%0,%1,%2,%3}, {%4,%5,%6,%7}, {%8,%9}, {%0,%1,%2,%3};"
            : "+f"(c00), "+f"(c01), "+f"(c02), "+f"(c03)
            : "r"(a0), "r"(a1), "r"(a2), "r"(a3), "r"(b00), "r"(b01));
        asm volatile(
            "mma.sync.aligned.m16n8k8.row.col.f32.tf32.tf32.f32 "
            "{%0,%1,%2,%3}, {%4,%5,%6,%7}, {%8,%9}, {%0,%1,%2,%3};"
            : "+f"(c10), "+f"(c11), "+f"(c12), "+f"(c13)
            : "r"(a0), "r"(a1), "r"(a2), "r"(a3), "r"(b10), "r"(b11));
    }

    const int r0 = row0 + gid;
    const int r1 = r0 + 8;
    {
        int col = nt0 * 8 + 2 * tig;
        float xi0 = Xism[gid * XI_STRIDE + col];
        float xi1 = Xism[gid * XI_STRIDE + col + 1];
        *reinterpret_cast<float2*>(out + (long)r0 * 128 + col) =
            make_float2(omb * xi0 + bb * c00, omb * xi1 + bb * c01);
        xi0 = Xism[(gid + 8) * XI_STRIDE + col];
        xi1 = Xism[(gid + 8) * XI_STRIDE + col + 1];
        *reinterpret_cast<float2*>(out + (long)r1 * 128 + col) =
            make_float2(omb * xi0 + bb * c02, omb * xi1 + bb * c03);

        col = nt1 * 8 + 2 * tig;
        xi0 = Xism[gid * XI_STRIDE + col];
        xi1 = Xism[gid * XI_STRIDE + col + 1];
        *reinterpret_cast<float2*>(out + (long)r0 * 128 + col) =
            make_float2(omb * xi0 + bb * c10, omb * xi1 + bb * c11);
        xi0 = Xism[(gid + 8) * XI_STRIDE + col];
        xi1 = Xism[(gid + 8) * XI_STRIDE + col + 1];
        *reinterpret_cast<float2*>(out + (long)r1 * 128 + col) =
            make_float2(omb * xi0 + bb * c12, omb * xi1 + bb * c13);
    }
}

// ---------------------------------------------------------------------------
// kernel_launch
// ---------------------------------------------------------------------------
extern "C" void kernel_launch(void* const* d_in, const int* in_sizes, int n_in,
                              void* d_out, int out_size) {
    const float* X     = (const float*)d_in[0];
    const float* X0    = (const float*)d_in[1];
    const float* degE  = (const float*)d_in[2];
    const float* degV  = (const float*)d_in[3];
    const float* alpha = (const float*)d_in[4];
    const float* beta  = (const float*)d_in[5];
    const float* W     = (const float*)d_in[6];
    const int*   g1s   = (const int*)d_in[7];
    const int*   g1d   = (const int*)d_in[8];
    const int*   g2s   = (const int*)d_in[9];
    const int*   g2d   = (const int*)d_in[10];
    float* out = (float*)d_out;

    // zero counters + ready flag + W prep
    prep_kernel<<<ZERO_BLKS + WPREP_BLKS, 256>>>(W);

    // CSR build: rank-recording hist -> fused scan -> atomic-free fill
    // (fill also converts X->fp16 in its stall shadow)
    hist_kernel<<<(NNZ / 4 + 255) / 256, 256>>>((const int4*)g1d, (const int4*)g2d);
    scan_fused_kernel<<<NBT, SCAN_TPB>>>();
    fill_kernel<<<FILL_BLKS, 256>>>((const int2*)g1s, (const int2*)g1d,
                                    (const int2*)g2s, (const int2*)g2d,
                                    (const float4*)X);

    // Gather-sum SpMMs (fp16 operands, fp16 pair-trees, fp32 accumulate)
    spmm1_kernel<<<(N_EDGES * 32 + 255) / 256, 256>>>(degE);
    spmm2_kernel<<<(N_NODES * 32 + 255) / 256, 256>>>((const float4*)X0, degV, alpha);

    // tf32 GEMM + residual epilogue (100000 = 6250 * 16 exact)
    gemm_kernel<<<N_NODES / 16, 256>>>(beta, out);
}